// round 12
// baseline (speedup 1.0000x reference)
#include <cuda_runtime.h>
#include <cstdint>

// Problem constants
#define BS   64
#define IC   256     // in_dim
#define NPIX 256     // pixels (I)
#define J    64      // out caps
#define D2   32      // dim per cap
#define NCHK 4       // i-chunks per batch in YD
#define CW   64      // chunk width (pixels)

// Global scratch (pred never materialized)
__device__ float g_L[(size_t)BS * J * NPIX];            // logits after iter-1
__device__ float g_xT[(size_t)BS * NPIX * IC];          // x transposed [b][i][ic]
__device__ float g_ypart[(size_t)BS * NCHK * J * IC];   // [b][ch][j][ic]
__device__ float g_cpart[(size_t)BS * NCHK * J];        // [b][ch][j]
__device__ float g_wt[(size_t)BS * J * IC];             // [b][j][ic]
__device__ float g_beta[(size_t)BS * J];                // [b][j]

// ---------------------------------------------------------------------------
// f32x2 helpers
// ---------------------------------------------------------------------------
#define FFMA2(acc, aa, bb) \
    asm("fma.rn.f32x2 %0, %1, %2, %0;" : "+l"(acc) : "l"(aa), "l"(bb))
__device__ __forceinline__ unsigned long long dup2f(float s) {
    unsigned long long d;
    asm("mov.b64 %0, {%1, %1};" : "=l"(d) : "f"(s));
    return d;
}
__device__ __forceinline__ float2 unpk(unsigned long long v) {
    float2 r;
    asm("mov.b64 {%0, %1}, %2;" : "=f"(r.x), "=f"(r.y) : "l"(v));
    return r;
}

// SMEM float offsets for yd_kernel
#define CSP    68                // cs row stride (multiple of 4: aligned float4)
#define XS_O   0                 // xs [ic=256][i=64]        16384
#define XT_O   16384             // xT [i=64][ic=256]        16384
#define WR_O   32768             // wt_raw [j=64][ic=256]    16384
#define CS_O   49152             // cs [i=64][j pad 68]      4352
#define LC_O   (CS_O + 64 * CSP) // Lc [j=64][i pad 65]      4160
#define SM_FLOATS (LC_O + 64 * 65)   // 57664 floats = 230,656 B

// ---------------------------------------------------------------------------
// Prep: transpose x[b][ic][i] -> g_xT[b][i][ic]  (runs once)
// ---------------------------------------------------------------------------
__global__ __launch_bounds__(256) void xt_prep(const float* __restrict__ x) {
    __shared__ float t[32][33];
    int b = blockIdx.z, i0 = blockIdx.x * 32, ic0 = blockIdx.y * 32;
    int tx = threadIdx.x, ty = threadIdx.y;   // 32 x 8
    #pragma unroll
    for (int q = 0; q < 4; q++)
        t[ty + q * 8][tx] = x[((size_t)b * IC + ic0 + ty + q * 8) * NPIX + i0 + tx];
    __syncthreads();
    #pragma unroll
    for (int q = 0; q < 4; q++) {
        int row = ty + q * 8;
        g_xT[((size_t)b * NPIX + i0 + row) * IC + ic0 + tx] = t[tx][row];
    }
}

// ---------------------------------------------------------------------------
// YD kernel: one CTA per (i-chunk, b), 512 threads. (R11-proven, transpose-free)
// ---------------------------------------------------------------------------
__global__ __launch_bounds__(512, 1) void yd_kernel(
    const float* __restrict__ x, const float* __restrict__ b_init, int it)
{
    extern __shared__ float sm[];
    float* xs = sm + XS_O;
    float* xT = sm + XT_O;
    float* wr = sm + WR_O;
    float* cs = sm + CS_O;
    float* Lc = sm + LC_O;

    const int ch  = blockIdx.x;
    const int b   = blockIdx.y;
    const int i0g = ch * CW;
    const int tid = threadIdx.x;

    // ---- loads (all coalesced) ----
    const float* xb = x + (size_t)b * IC * NPIX + i0g;
    for (int e = tid; e < IC * CW; e += 512) {
        int ic = e >> 6, il = e & 63;
        xs[ic * 64 + il] = xb[(size_t)ic * NPIX + il];
    }
    const float* xTb = g_xT + ((size_t)b * NPIX + i0g) * IC;
    for (int e = tid; e < CW * IC; e += 512)
        xT[e] = xTb[e];
    if (it) {
        const float* wsrc = g_wt + (size_t)b * J * IC;
        for (int e = tid; e < J * IC; e += 512)
            wr[e] = wsrc[e];
    } else {
        for (int e = tid; e < J * CW; e += 512) {
            int j = e >> 6, il = e & 63;
            Lc[j * 65 + il] = b_init[((size_t)b * J + j) * NPIX + i0g + il];
        }
    }
    __syncthreads();

    // ---- db GEMM: M=64(j) x N=64(i), K=256(ic); tile 2j x 4i ----
    if (it) {
        const int ty = tid >> 4, tx = tid & 15;
        const int j0 = ty * 2, il0 = tx * 4;
        unsigned long long acc[2][2] = {{0ull, 0ull}, {0ull, 0ull}};
        const float* w0p = wr + j0 * IC;
        const float* w1p = wr + (j0 + 1) * IC;
        #pragma unroll 4
        for (int k = 0; k < IC; k++) {
            ulonglong2 b2 = *reinterpret_cast<const ulonglong2*>(xs + k * 64 + il0);
            unsigned long long ad0 = dup2f(w0p[k]);
            unsigned long long ad1 = dup2f(w1p[k]);
            FFMA2(acc[0][0], ad0, b2.x); FFMA2(acc[0][1], ad0, b2.y);
            FFMA2(acc[1][0], ad1, b2.x); FFMA2(acc[1][1], ad1, b2.y);
        }
        const float* Lsrc = (it == 2) ? g_L : b_init;
        #pragma unroll
        for (int r = 0; r < 2; r++) {
            int j = j0 + r;
            float be = g_beta[b * J + j];
            const float* Ls = Lsrc + ((size_t)b * J + j) * NPIX + i0g + il0;
            float2 lo = unpk(acc[r][0]), hi = unpk(acc[r][1]);
            float l0 = Ls[0] + lo.x + be;
            float l1 = Ls[1] + lo.y + be;
            float l2 = Ls[2] + hi.x + be;
            float l3 = Ls[3] + hi.y + be;
            float* Ld = Lc + j * 65 + il0;
            Ld[0] = l0; Ld[1] = l1; Ld[2] = l2; Ld[3] = l3;
            if (it == 1) {
                float* Lg = g_L + ((size_t)b * J + j) * NPIX + i0g + il0;
                Lg[0] = l0; Lg[1] = l1; Lg[2] = l2; Lg[3] = l3;
            }
        }
        __syncthreads();
    }

    // ---- softmax over j per pixel: 8 threads per pixel, shfl reduce ----
    {
        int i = tid >> 3, sub = tid & 7, jb = sub * 8;
        float m = -1e30f;
        #pragma unroll
        for (int jj = 0; jj < 8; jj++)
            m = fmaxf(m, Lc[(jb + jj) * 65 + i]);
        #pragma unroll
        for (int o = 1; o < 8; o <<= 1)
            m = fmaxf(m, __shfl_xor_sync(0xFFFFFFFFu, m, o));
        float ssum = 0.f;
        #pragma unroll
        for (int jj = 0; jj < 8; jj++) {
            float e = __expf(Lc[(jb + jj) * 65 + i] - m);
            cs[i * CSP + jb + jj] = e;
            ssum += e;
        }
        #pragma unroll
        for (int o = 1; o < 8; o <<= 1)
            ssum += __shfl_xor_sync(0xFFFFFFFFu, ssum, o);
        float rd = 1.0f / ssum;
        #pragma unroll
        for (int jj = 0; jj < 8; jj++)
            cs[i * CSP + jb + jj] *= rd;
    }
    __syncthreads();

    // ---- Csum partial per j ----
    if (tid < J) {
        float cc = 0.f;
        #pragma unroll 8
        for (int i2 = 0; i2 < CW; i2++) cc += cs[i2 * CSP + tid];
        g_cpart[((size_t)b * NCHK + ch) * J + tid] = cc;
    }

    // ---- y GEMM: M=64(j) x N=256(ic), K=64(i); tile 4j x 8ic ----
    {
        const int ty = tid >> 5, tx = tid & 31;
        const int j0 = ty * 4, ic0 = tx * 8;
        unsigned long long acc[4][4];
        #pragma unroll
        for (int r = 0; r < 4; r++)
            #pragma unroll
            for (int p = 0; p < 4; p++) acc[r][p] = 0ull;

        for (int k = 0; k < CW; k++) {
            float4 c4 = *reinterpret_cast<const float4*>(cs + k * CSP + j0);
            const ulonglong2* bq = reinterpret_cast<const ulonglong2*>(xT + k * 256 + ic0);
            ulonglong2 b0 = bq[0], b1 = bq[1];
            unsigned long long ad;
            ad = dup2f(c4.x);
            FFMA2(acc[0][0], ad, b0.x); FFMA2(acc[0][1], ad, b0.y);
            FFMA2(acc[0][2], ad, b1.x); FFMA2(acc[0][3], ad, b1.y);
            ad = dup2f(c4.y);
            FFMA2(acc[1][0], ad, b0.x); FFMA2(acc[1][1], ad, b0.y);
            FFMA2(acc[1][2], ad, b1.x); FFMA2(acc[1][3], ad, b1.y);
            ad = dup2f(c4.z);
            FFMA2(acc[2][0], ad, b0.x); FFMA2(acc[2][1], ad, b0.y);
            FFMA2(acc[2][2], ad, b1.x); FFMA2(acc[2][3], ad, b1.y);
            ad = dup2f(c4.w);
            FFMA2(acc[3][0], ad, b0.x); FFMA2(acc[3][1], ad, b0.y);
            FFMA2(acc[3][2], ad, b1.x); FFMA2(acc[3][3], ad, b1.y);
        }
        float* ybase = g_ypart + (((size_t)b * NCHK + ch) * J + j0) * IC + ic0;
        #pragma unroll
        for (int r = 0; r < 4; r++) {
            float* yr = ybase + (size_t)r * IC;
            #pragma unroll
            for (int p = 0; p < 2; p++) {
                float2 e0 = unpk(acc[r][2 * p]);
                float2 e1 = unpk(acc[r][2 * p + 1]);
                *reinterpret_cast<float4*>(yr + p * 4) =
                    make_float4(e0.x, e0.y, e1.x, e1.y);
            }
        }
    }
}

// ---------------------------------------------------------------------------
// S kernel (redesigned): one CTA per (j, 16-batch group), 256 threads.
// smem: Wj[32][260], ysm[16][260], vsm/ssm[16][33], Cs, Wbj.
// ---------------------------------------------------------------------------
#define WJ_O2   0
#define YS_O2   8320
#define VS_O2   12480
#define SS_O2   13008
#define CS_O2   13536
#define WB_O2   13552
#define S_SM_FLOATS 13584        // 54,336 B

__global__ __launch_bounds__(256) void s_kernel(
    const float* __restrict__ W, const float* __restrict__ Wb,
    float* __restrict__ out, int final_it)
{
    extern __shared__ float ss[];
    float* Wj  = ss + WJ_O2;
    float* ysm = ss + YS_O2;
    float* vsm = ss + VS_O2;
    float* ssm = ss + SS_O2;
    float* Cs  = ss + CS_O2;
    float* Wbj = ss + WB_O2;

    const int j   = blockIdx.x;
    const int b0  = blockIdx.y * 16;
    const int tid = threadIdx.x;

    // stage Wj (row-padded), y (chunk-reduced), C, Wb
    for (int e = tid; e < D2 * IC; e += 256) {
        int d = e >> 8, ic = e & 255;
        Wj[d * 260 + ic] = W[(size_t)j * D2 * IC + e];
    }
    if (tid < D2) Wbj[tid] = Wb[j * D2 + tid];
    for (int e = tid; e < 16 * IC; e += 256) {
        int b = e >> 8, ic = e & 255;
        const float* yp = g_ypart + (((size_t)(b0 + b) * NCHK) * J + j) * IC + ic;
        ysm[b * 260 + ic] = (yp[0] + yp[(size_t)J * IC])
                          + (yp[2 * (size_t)J * IC] + yp[3 * (size_t)J * IC]);
    }
    if (tid < 16) {
        const float* cp = g_cpart + ((size_t)(b0 + tid) * NCHK) * J + j;
        Cs[tid] = (cp[0] + cp[J]) + (cp[2 * J] + cp[3 * J]);
    }
    __syncthreads();

    // stage2: s[b][d] = Wj[d,:].y[b,:] + Wb[d]*C[b].  thread -> (b, d-pair)
    {
        int b = tid & 15, d0 = (tid >> 4) * 2;
        const float* y  = ysm + b * 260;
        const float* w0 = Wj + d0 * 260;
        const float* w1 = w0 + 260;
        float a0 = 0.f, a1 = 0.f;
        #pragma unroll 8
        for (int ic = 0; ic < IC; ic += 4) {
            float4 y4 = *reinterpret_cast<const float4*>(y + ic);
            float4 wa = *reinterpret_cast<const float4*>(w0 + ic);
            float4 wb = *reinterpret_cast<const float4*>(w1 + ic);
            a0 += y4.x * wa.x + y4.y * wa.y + y4.z * wa.z + y4.w * wa.w;
            a1 += y4.x * wb.x + y4.y * wb.y + y4.z * wb.z + y4.w * wb.w;
        }
        float C = Cs[b];
        ssm[b * 33 + d0]     = a0 + Wbj[d0] * C;
        ssm[b * 33 + d0 + 1] = a1 + Wbj[d0 + 1] * C;
    }
    __syncthreads();

    // squash: warp w handles b = 2w, 2w+1; lane = d
    {
        int w = tid >> 5, lane = tid & 31;
        #pragma unroll
        for (int h = 0; h < 2; h++) {
            int b = w * 2 + h;
            float sv = ssm[b * 33 + lane];
            float sq = sv * sv;
            #pragma unroll
            for (int o = 16; o; o >>= 1) sq += __shfl_xor_sync(0xFFFFFFFFu, sq, o);
            float scale = (sq / (1.0f + sq)) * rsqrtf(sq + 1e-8f);
            float vv = scale * sv;
            vsm[b * 33 + lane] = vv;
            if (final_it) out[((size_t)(b0 + b) * J + j) * D2 + lane] = vv;
            float bt = vv * Wbj[lane];
            #pragma unroll
            for (int o = 16; o; o >>= 1) bt += __shfl_xor_sync(0xFFFFFFFFu, bt, o);
            if (lane == 0) g_beta[(b0 + b) * J + j] = bt;
        }
    }
    __syncthreads();

    // stage4: wt[b][ic] = sum_d v[b][d] * Wj[d][ic].  thread = ic.
    if (!final_it) {
        int ic = tid;
        float wv[16];
        #pragma unroll
        for (int b = 0; b < 16; b++) wv[b] = 0.f;
        #pragma unroll 4
        for (int d = 0; d < D2; d++) {
            float wjv = Wj[d * 260 + ic];
            #pragma unroll
            for (int b = 0; b < 16; b++)
                wv[b] = fmaf(vsm[b * 33 + d], wjv, wv[b]);
        }
        #pragma unroll
        for (int b = 0; b < 16; b++)
            g_wt[((size_t)(b0 + b) * J + j) * IC + ic] = wv[b];
    }
}

// ---------------------------------------------------------------------------
// Launch (7 kernels, graph-capturable, allocation-free)
// Inputs: x[64,256,16,16] f32, b_init[64,64,256] f32, W[2048,256] f32, Wb[2048] f32
// Output: v[64,64,32] f32
// ---------------------------------------------------------------------------
extern "C" void kernel_launch(void* const* d_in, const int* in_sizes, int n_in,
                              void* d_out, int out_size)
{
    const float* x      = (const float*)d_in[0];
    const float* b_init = (const float*)d_in[1];
    const float* W      = (const float*)d_in[2];
    const float* Wb     = (const float*)d_in[3];
    float* out = (float*)d_out;

    const int ysmem = SM_FLOATS * (int)sizeof(float);     // 230,656 B
    const int ssmem = S_SM_FLOATS * (int)sizeof(float);   // 54,336 B
    cudaFuncSetAttribute(yd_kernel, cudaFuncAttributeMaxDynamicSharedMemorySize, ysmem);
    cudaFuncSetAttribute(s_kernel,  cudaFuncAttributeMaxDynamicSharedMemorySize, ssmem);

    xt_prep<<<dim3(NPIX / 32, IC / 32, BS), dim3(32, 8)>>>(x);

    dim3 ygrid(NCHK, BS);      // 4 x 64 = 256 CTAs
    dim3 sgrid(J, 4);          // 64 x 4  = 256 CTAs (16 b each)

    yd_kernel<<<ygrid, 512, ysmem>>>(x, b_init, 0);
    s_kernel<<<sgrid, 256, ssmem>>>(W, Wb, out, 0);
    yd_kernel<<<ygrid, 512, ysmem>>>(x, b_init, 1);
    s_kernel<<<sgrid, 256, ssmem>>>(W, Wb, out, 0);
    yd_kernel<<<ygrid, 512, ysmem>>>(x, b_init, 2);
    s_kernel<<<sgrid, 256, ssmem>>>(W, Wb, out, 1);
}